// round 2
// baseline (speedup 1.0000x reference)
#include <cuda_runtime.h>
#include <math.h>

// ---------------- problem constants ----------------
#define NN      100000
#define EE      1600000
#define HH      64
#define FINW    16
#define LL      3
#define KLUT    1024
#define CUT     5.0f
#define BN_INV  0.9995003749f   // 1/sqrt(1+1e-3)

// ---------------- device scratch (no allocation allowed) ----------------
__device__ float4 g_h[NN * 16];        // node features [N,64] as float4
__device__ float4 g_agg[NN * 16];      // aggregation buffer
__device__ float4 g_csr[EE];           // CSR entries: {col(int bits), fs0, fs1, fs2}
__device__ int    g_deg[NN];
__device__ int    g_rowstart[NN];
__device__ int    g_cursor[NN];
__device__ int    g_bsums[128];
__device__ float  g_w2s[LL * HH];
__device__ float  g_b2s[LL];
__device__ float  g_lut[LL * (KLUT + 1)];
__device__ float  g_gsum[HH];

__device__ __forceinline__ float sp(float x) {
    return fmaxf(x, 0.f) + log1pf(__expf(-fabsf(x)));
}

// ---------------- embedding: h = x @ emb_W + emb_b ----------------
__global__ void k_embed(const float* __restrict__ x,
                        const float* __restrict__ W,
                        const float* __restrict__ b) {
    int idx = blockIdx.x * blockDim.x + threadIdx.x;
    if (idx >= NN * HH) return;
    int n = idx >> 6, j = idx & 63;
    float acc = b[j];
    const float* xr = x + n * FINW;
#pragma unroll
    for (int k = 0; k < FINW; k++) acc += xr[k] * W[k * HH + j];
    ((float*)g_h)[idx] = acc;
}

// ---------------- filter-MLP collapse: w2s[l][k] = sum_j fW2[l][k][j] ----------------
__global__ void k_prep1(const float* __restrict__ fW2, const float* __restrict__ fb2) {
    int l = blockIdx.x, k = threadIdx.x;
    const float* wr = fW2 + l * HH * HH + k * HH;
    float s = 0.f;
#pragma unroll
    for (int j = 0; j < HH; j++) s += wr[j];
    g_w2s[l * HH + k] = s;
    if (k == 0) {
        float t = 0.f;
        for (int j = 0; j < HH; j++) t += fb2[l * HH + j];
        g_b2s[l] = t;
    }
}

// ---------------- LUT build (exact tanhf) ----------------
__global__ void k_lut(const float* __restrict__ fW1, const float* __restrict__ fb1) {
    int idx = blockIdx.x * blockDim.x + threadIdx.x;
    if (idx >= LL * (KLUT + 1)) return;
    int l = idx / (KLUT + 1), i = idx % (KLUT + 1);
    float s = -1.f + 2.f * (float)i / (float)KLUT;
    float acc = g_b2s[l];
    const float* a = fW1 + l * HH;
    const float* b = fb1 + l * HH;
    const float* c = g_w2s + l * HH;
#pragma unroll 8
    for (int k = 0; k < HH; k++) acc += tanhf(s * a[k] + b[k]) * c[k];
    g_lut[idx] = acc;
}

// ---------------- histogram of row ids ----------------
__global__ void k_hist(const int* __restrict__ row) {
    int e = blockIdx.x * blockDim.x + threadIdx.x;
    if (e < EE) atomicAdd(&g_deg[row[e]], 1);
}

// ---------------- 3-kernel exclusive scan over deg[N] ----------------
__global__ void k_scan_a() {
    __shared__ int s[256];
    int b = blockIdx.x, acc = 0;
    for (int i = threadIdx.x; i < 1024; i += 256) {
        int g = b * 1024 + i;
        if (g < NN) acc += g_deg[g];
    }
    s[threadIdx.x] = acc; __syncthreads();
    for (int off = 128; off > 0; off >>= 1) {
        if (threadIdx.x < off) s[threadIdx.x] += s[threadIdx.x + off];
        __syncthreads();
    }
    if (threadIdx.x == 0) g_bsums[b] = s[0];
}
__global__ void k_scan_b(int nb) {
    __shared__ int s[128];
    int t = threadIdx.x;
    int v = (t < nb) ? g_bsums[t] : 0;
    s[t] = v; __syncthreads();
    for (int off = 1; off < 128; off <<= 1) {
        int add = (t >= off) ? s[t - off] : 0;
        __syncthreads();
        s[t] += add;
        __syncthreads();
    }
    if (t < nb) g_bsums[t] = s[t] - v;  // exclusive
}
__global__ void k_scan_c() {
    __shared__ int s[1024];
    int b = blockIdx.x, t = threadIdx.x, g = b * 1024 + t;
    int v = (g < NN) ? g_deg[g] : 0;
    s[t] = v; __syncthreads();
    for (int off = 1; off < 1024; off <<= 1) {
        int add = (t >= off) ? s[t - off] : 0;
        __syncthreads();
        s[t] += add;
        __syncthreads();
    }
    if (g < NN) g_rowstart[g] = s[t] - v + g_bsums[b];
}

// ---------------- permute edges into CSR order, computing fs inline ----------------
__global__ void k_permute(const int* __restrict__ row, const int* __restrict__ col,
                          const float* __restrict__ dist) {
    __shared__ float slut[LL * (KLUT + 1)];
    for (int i = threadIdx.x; i < LL * (KLUT + 1); i += blockDim.x) slut[i] = g_lut[i];
    __syncthreads();
    for (int e = blockIdx.x * blockDim.x + threadIdx.x; e < EE;
         e += gridDim.x * blockDim.x) {
        float d = dist[e];
        float cut = (d <= CUT) ? 0.5f * (__cosf(d * (float)(M_PI / 5.0)) + 1.f) : 0.f;
        float s = d * (2.f / CUT) - 1.f;
        float xx = (s + 1.f) * (0.5f * (float)KLUT);
        xx = fminf(fmaxf(xx, 0.f), (float)KLUT - 0.001f);
        int i0 = (int)xx;
        float fr = xx - (float)i0;
        float v0a = slut[i0],            v0b = slut[i0 + 1];
        float v1a = slut[1025 + i0],     v1b = slut[1025 + i0 + 1];
        float v2a = slut[2050 + i0],     v2b = slut[2050 + i0 + 1];
        float f0 = cut * (v0a + fr * (v0b - v0a));
        float f1 = cut * (v1a + fr * (v1b - v1a));
        float f2 = cut * (v2a + fr * (v2b - v2a));
        int r = row[e], c = col[e];
        int pos = atomicAdd(&g_cursor[r], 1);
        g_csr[pos] = make_float4(__int_as_float(c), f0, f1, f2);
    }
}

// ---------------- gather-side aggregation: agg[n] = sum_e h[col]*fs ----------------
__global__ void k_gather(int layer) {
    int t = blockIdx.x * blockDim.x + threadIdx.x;
    int node = t >> 4, lane = t & 15;
    if (node >= NN) return;
    int start = g_rowstart[node];
    int d = g_deg[node];
    float4 acc = make_float4(0.f, 0.f, 0.f, 0.f);
    for (int i = 0; i < d; i++) {
        float4 ent = g_csr[start + i];
        int c = __float_as_int(ent.x);
        float f = (layer == 0) ? ent.y : (layer == 1) ? ent.z : ent.w;
        float4 hx = g_h[c * 16 + lane];
        acc.x += hx.x * f; acc.y += hx.y * f;
        acc.z += hx.z * f; acc.w += hx.w * f;
    }
    g_agg[node * 16 + lane] = acc;
}

// ---------------- node update: h += BN(softplus(agg@W1+b1)@W2+b2) ----------------
// 128 threads = 128 nodes/block; each thread: 2 nodes x 32 outputs (8 FFMA/weight-load)
__global__ void __launch_bounds__(128) k_nodeup(
    const float* __restrict__ iW1, const float* __restrict__ ib1,
    const float* __restrict__ iW2, const float* __restrict__ ib2,
    const float* __restrict__ gam, const float* __restrict__ bet, int l) {
    __shared__ float sA[128][65];
    int base = blockIdx.x * 128;
    const float* agg = (const float*)g_agg;
    for (int idx = threadIdx.x; idx < 128 * 64; idx += 128) {
        int n = idx >> 6, k = idx & 63, gn = base + n;
        sA[n][k] = (gn < NN) ? agg[gn * 64 + k] : 0.f;
    }
    __syncthreads();

    int tc = threadIdx.x & 63;
    int half = threadIdx.x >> 6;
    int jb = half * 32;
    int n0 = 2 * tc, n1 = n0 + 1;

    float a0[32], a1[32];
#pragma unroll
    for (int j = 0; j < 32; j++) { float bv = ib1[l * 64 + jb + j]; a0[j] = bv; a1[j] = bv; }

    const float* W1 = iW1 + l * 4096;
#pragma unroll 4
    for (int k = 0; k < 64; k++) {
        float x0 = sA[n0][k], x1 = sA[n1][k];
        const float4* wr = (const float4*)(W1 + k * 64 + jb);
#pragma unroll
        for (int q = 0; q < 8; q++) {
            float4 w = __ldg(wr + q);
            a0[4*q+0] += x0 * w.x; a0[4*q+1] += x0 * w.y;
            a0[4*q+2] += x0 * w.z; a0[4*q+3] += x0 * w.w;
            a1[4*q+0] += x1 * w.x; a1[4*q+1] += x1 * w.y;
            a1[4*q+2] += x1 * w.z; a1[4*q+3] += x1 * w.w;
        }
    }
    __syncthreads();
#pragma unroll
    for (int j = 0; j < 32; j++) {
        sA[n0][jb + j] = sp(a0[j]);
        sA[n1][jb + j] = sp(a1[j]);
    }
    __syncthreads();

#pragma unroll
    for (int j = 0; j < 32; j++) { float bv = ib2[l * 64 + jb + j]; a0[j] = bv; a1[j] = bv; }
    const float* W2 = iW2 + l * 4096;
#pragma unroll 4
    for (int k = 0; k < 64; k++) {
        float x0 = sA[n0][k], x1 = sA[n1][k];
        const float4* wr = (const float4*)(W2 + k * 64 + jb);
#pragma unroll
        for (int q = 0; q < 8; q++) {
            float4 w = __ldg(wr + q);
            a0[4*q+0] += x0 * w.x; a0[4*q+1] += x0 * w.y;
            a0[4*q+2] += x0 * w.z; a0[4*q+3] += x0 * w.w;
            a1[4*q+0] += x1 * w.x; a1[4*q+1] += x1 * w.y;
            a1[4*q+2] += x1 * w.z; a1[4*q+3] += x1 * w.w;
        }
    }

    float* h = (float*)g_h;
    int gn0 = base + n0, gn1 = base + n1;
    if (gn0 < NN) {
#pragma unroll
        for (int j = 0; j < 32; j++) {
            int idx = gn0 * 64 + jb + j;
            h[idx] += a0[j] * BN_INV * gam[l * 64 + jb + j] + bet[l * 64 + jb + j];
        }
    }
    if (gn1 < NN) {
#pragma unroll
        for (int j = 0; j < 32; j++) {
            int idx = gn1 * 64 + jb + j;
            h[idx] += a1[j] * BN_INV * gam[l * 64 + jb + j] + bet[l * 64 + jb + j];
        }
    }
}

// ---------------- column mean of h ----------------
__global__ void k_mean() {
    int j = threadIdx.x & 63, r = threadIdx.x >> 6;
    const float* h = (const float*)g_h;
    float acc = 0.f;
    for (int n = blockIdx.x * 4 + r; n < NN; n += gridDim.x * 4)
        acc += h[n * 64 + j];
    __shared__ float s[256];
    s[threadIdx.x] = acc; __syncthreads();
    if (r == 0)
        atomicAdd(&g_gsum[j], s[j] + s[64 + j] + s[128 + j] + s[192 + j]);
}

// ---------------- final tiny MLP chain -> out[3] ----------------
__global__ void k_final(const float* __restrict__ oW1, const float* __restrict__ ob1,
                        const float* __restrict__ og1, const float* __restrict__ obt1,
                        const float* __restrict__ oW2, const float* __restrict__ ob2,
                        const float* __restrict__ og2, const float* __restrict__ obt2,
                        const float* __restrict__ finW, const float* __restrict__ finb,
                        float* __restrict__ out) {
    __shared__ float sg[64], s1[32], s2[32];
    int t = threadIdx.x;
    if (t < 64) sg[t] = g_gsum[t] * (1.f / (float)NN);
    __syncthreads();
    if (t < 32) {
        float acc = ob1[t];
        for (int k = 0; k < 64; k++) acc += sg[k] * oW1[k * 32 + t];
        s1[t] = sp(acc) * BN_INV * og1[t] + obt1[t];
    }
    __syncthreads();
    if (t < 32) {
        float acc = ob2[t];
        for (int k = 0; k < 32; k++) acc += s1[k] * oW2[k * 32 + t];
        s2[t] = sp(acc) * BN_INV * og2[t] + obt2[t];
    }
    __syncthreads();
    if (t < 3) {
        float acc = finb[t];
        for (int k = 0; k < 32; k++) acc += s2[k] * finW[k * 3 + t];
        out[t] = acc;
    }
}

// ---------------- launch ----------------
extern "C" void kernel_launch(void* const* d_in, const int* in_sizes, int n_in,
                              void* d_out, int out_size) {
    const float* x    = (const float*)d_in[0];
    const int*   ei   = (const int*)d_in[1];
    const float* dist = (const float*)d_in[2];
    // d_in[3] edge_attr: unused by reference
    const float* embW = (const float*)d_in[4];
    const float* embB = (const float*)d_in[5];
    const float* fW1  = (const float*)d_in[6];
    const float* fb1  = (const float*)d_in[7];
    const float* fW2  = (const float*)d_in[8];
    const float* fb2  = (const float*)d_in[9];
    const float* iW1  = (const float*)d_in[10];
    const float* ib1  = (const float*)d_in[11];
    const float* iW2  = (const float*)d_in[12];
    const float* ib2  = (const float*)d_in[13];
    const float* gam  = (const float*)d_in[14];
    const float* bet  = (const float*)d_in[15];
    const float* oW1  = (const float*)d_in[16];
    const float* ob1  = (const float*)d_in[17];
    const float* og1  = (const float*)d_in[18];
    const float* obt1 = (const float*)d_in[19];
    const float* oW2  = (const float*)d_in[20];
    const float* ob2  = (const float*)d_in[21];
    const float* og2  = (const float*)d_in[22];
    const float* obt2 = (const float*)d_in[23];
    const float* finW = (const float*)d_in[24];
    const float* finb = (const float*)d_in[25];
    float* out = (float*)d_out;

    const int* row = ei;        // edge_index[0]
    const int* col = ei + EE;   // edge_index[1]

    void *p_deg, *p_rowstart, *p_cursor, *p_gsum;
    cudaGetSymbolAddress(&p_deg, g_deg);
    cudaGetSymbolAddress(&p_rowstart, g_rowstart);
    cudaGetSymbolAddress(&p_cursor, g_cursor);
    cudaGetSymbolAddress(&p_gsum, g_gsum);

    cudaMemsetAsync(p_deg, 0, NN * sizeof(int));
    cudaMemsetAsync(p_gsum, 0, HH * sizeof(float));

    k_embed<<<(NN * HH + 255) / 256, 256>>>(x, embW, embB);
    k_prep1<<<LL, HH>>>(fW2, fb2);
    k_lut<<<(LL * (KLUT + 1) + 127) / 128, 128>>>(fW1, fb1);

    k_hist<<<(EE + 255) / 256, 256>>>(row);
    int nb = (NN + 1023) / 1024;           // 98
    k_scan_a<<<nb, 256>>>();
    k_scan_b<<<1, 128>>>(nb);
    k_scan_c<<<nb, 1024>>>();
    cudaMemcpyAsync(p_cursor, p_rowstart, NN * sizeof(int),
                    cudaMemcpyDeviceToDevice);
    k_permute<<<4096, 256>>>(row, col, dist);

    for (int l = 0; l < LL; l++) {
        k_gather<<<(NN * 16 + 255) / 256, 256>>>(l);
        k_nodeup<<<(NN + 127) / 128, 128>>>(iW1, ib1, iW2, ib2, gam, bet, l);
    }

    k_mean<<<240, 256>>>();
    k_final<<<1, 64>>>(oW1, ob1, og1, obt1, oW2, ob2, og2, obt2, finW, finb, out);
}